// round 13
// baseline (speedup 1.0000x reference)
#include <cuda_runtime.h>
#include <cuda_fp16.h>
#include <cstdint>

// ---------------------------------------------------------------------------
// QuantizedLinear: Y[8192,11008] = X[8192,4096] @ dequant(W)^T + bias
// tcgen05 is NOT available (harness PTX target is plain sm_103), so this uses
// warp-level mma.sync (HMMA) with an fp16 2-pass precision scheme:
//   wh = fp16(w), wl = fp16(w - wh);  y = x16 @ (wh + wl)^T  (K concatenated)
// Residual error = x fp16 quantization only (~3e-4 L2 rel err).
//
// R12 fix: B operand ldmatrix must be NON-trans. Smem B tile is [n][k]
// row-major == K x N col-major, which is exactly the mma.row.col B fragment
// layout when loaded without .trans. The .trans in R11 fed the MMA a
// transposed fragment (rel_err 1.32).
// ---------------------------------------------------------------------------

#define TOK   8192
#define INF   4096
#define OUTF  11008

#define BK      32
#define STAGES  4
#define ROWB    80                  // padded smem row stride (5 x 16B chunks)
#define ASTG    (128 * ROWB)        // 10240 B per A tile
#define STGB    (2 * ASTG)          // 20480 B per stage (A + B)
#define SMEM_BYTES (STAGES * STGB)  // 81920
#define KT_TOT  256                 // 2 passes x 128 k-tiles

// prepped operands (module-load-time scratch; no runtime alloc)
__device__ __align__(128) __half g_X [(size_t)TOK  * INF];   // 67 MB
__device__ __align__(128) __half g_WH[(size_t)OUTF * INF];   // 90 MB
__device__ __align__(128) __half g_WL[(size_t)OUTF * INF];   // 90 MB

// -------------------- prep: x -> fp16 ---------------------------------------
__global__ void convert_x_kernel(const float* __restrict__ x) {
    size_t e = ((size_t)blockIdx.x * 256 + threadIdx.x) * 4;
    float4 v = *reinterpret_cast<const float4*>(x + e);
    __half2 p0 = __halves2half2(__float2half_rn(v.x), __float2half_rn(v.y));
    __half2 p1 = __halves2half2(__float2half_rn(v.z), __float2half_rn(v.w));
    uint2 pk = make_uint2(*reinterpret_cast<uint32_t*>(&p0),
                          *reinterpret_cast<uint32_t*>(&p1));
    *reinterpret_cast<uint2*>(g_X + e) = pk;
}

// -------------------- prep: dequant + hi/lo split of W ----------------------
__global__ void dequant_w_kernel(const int* __restrict__ qw,
                                 const float* __restrict__ scales,
                                 const float* __restrict__ zeros) {
    size_t wi = ((size_t)blockIdx.x * 256 + threadIdx.x) * 4;
    int o  = (int)(wi >> 12);        // output feature
    int i0 = (int)(wi & 4095);       // input channel base (multiple of 4)
    int2 qq = *reinterpret_cast<const int2*>(qw + (size_t)o * 2048 + (i0 >> 1));
    int g = i0 >> 7;                 // group of 128 (same for all 4 cols)
    float s = scales[o * 32 + g];
    float z = zeros [o * 32 + g];
    float w[4];
    w[0] = ((float)( qq.x       & 15) - z) * s;   // col 2i   = low nibble
    w[1] = ((float)((qq.x >> 4) & 15) - z) * s;   // col 2i+1 = high nibble
    w[2] = ((float)( qq.y       & 15) - z) * s;
    w[3] = ((float)((qq.y >> 4) & 15) - z) * s;
    unsigned short h[4], l[4];
#pragma unroll
    for (int k = 0; k < 4; k++) {
        __half hh = __float2half_rn(w[k]);
        __half ll = __float2half_rn(w[k] - __half2float(hh));
        h[k] = __half_as_ushort(hh);
        l[k] = __half_as_ushort(ll);
    }
    size_t off = (size_t)o * INF + i0;
    *reinterpret_cast<uint2*>(g_WH + off) =
        make_uint2((uint32_t)h[0] | ((uint32_t)h[1] << 16),
                   (uint32_t)h[2] | ((uint32_t)h[3] << 16));
    *reinterpret_cast<uint2*>(g_WL + off) =
        make_uint2((uint32_t)l[0] | ((uint32_t)l[1] << 16),
                   (uint32_t)l[2] | ((uint32_t)l[3] << 16));
}

// -------------------- GEMM helpers ------------------------------------------
#define LDSM4(R, addr)                                                        \
    asm volatile("ldmatrix.sync.aligned.m8n8.x4.shared.b16 {%0,%1,%2,%3}, [%4];" \
        : "=r"((R)[0]), "=r"((R)[1]), "=r"((R)[2]), "=r"((R)[3]) : "r"(addr))

#define MMA16816(C, A, B0, B1)                                                \
    asm volatile("mma.sync.aligned.m16n8k16.row.col.f32.f16.f16.f32 "         \
        "{%0,%1,%2,%3}, {%4,%5,%6,%7}, {%8,%9}, {%0,%1,%2,%3};"               \
        : "+f"((C)[0]), "+f"((C)[1]), "+f"((C)[2]), "+f"((C)[3])              \
        : "r"((A)[0]), "r"((A)[1]), "r"((A)[2]), "r"((A)[3]),                 \
          "r"(B0), "r"(B1))

static __device__ __forceinline__ void issue_stage(
    int kt, int tid, uint32_t sbase,
    const __half* __restrict__ Agm,
    const __half* __restrict__ BgmH,
    const __half* __restrict__ BgmL)
{
    if (kt < KT_TOT) {
        uint32_t st = sbase + (uint32_t)(kt & 3) * STGB;
        const __half* Bg = (kt < 128) ? BgmH : BgmL;
        int kOff = (kt & 127) * BK;
#pragma unroll
        for (int j = 0; j < 2; j++) {
            int ch  = tid + j * 256;      // 512 16B-chunks per operand tile
            int row = ch >> 2;
            int c   = ch & 3;
            const void* asrc = Agm + (size_t)row * INF + kOff + c * 8;
            uint32_t    adst = st + row * ROWB + c * 16;
            asm volatile("cp.async.cg.shared.global [%0], [%1], 16;"
                         :: "r"(adst), "l"(asrc));
            const void* bsrc = Bg + (size_t)row * INF + kOff + c * 8;
            uint32_t    bdst = st + ASTG + row * ROWB + c * 16;
            asm volatile("cp.async.cg.shared.global [%0], [%1], 16;"
                         :: "r"(bdst), "l"(bsrc));
        }
    }
    asm volatile("cp.async.commit_group;" ::: "memory");
}

// -------------------- GEMM kernel -------------------------------------------
// CTA 128x128, 8 warps (4m x 2n), warp tile 32x64, BK=32, 4-stage cp.async.
__global__ void __launch_bounds__(256, 2)
gemm_kernel(const float* __restrict__ bias, float* __restrict__ out) {
    extern __shared__ __align__(1024) uint8_t smem[];
    const int tid  = threadIdx.x;
    const int lane = tid & 31;
    const int wid  = tid >> 5;
    const int wm   = wid >> 1;         // 0..3
    const int wn   = wid & 1;          // 0..1

    // supertile raster: bands of 16 m-tiles, sweep all 86 n-tiles per band
    const int bid   = blockIdx.x;
    const int band  = bid / (16 * 86);
    const int rem   = bid % (16 * 86);
    const int ntile = rem >> 4;
    const int mtile = band * 16 + (rem & 15);
    const int mBase = mtile * 128;
    const int nBase = ntile * 128;

    const __half* Agm  = g_X  + (size_t)mBase * INF;
    const __half* BgmH = g_WH + (size_t)nBase * INF;
    const __half* BgmL = g_WL + (size_t)nBase * INF;

    const uint32_t sbase = (uint32_t)__cvta_generic_to_shared(smem);

    // per-lane ldmatrix row addresses (80B rows => (5r+c)%8 covers all banks)
    // A (16x16 per ldsm.x4): m0 rows0-7/k0-7, m1 rows8-15/k0-7,
    //                        m2 rows0-7/k8-15, m3 rows8-15/k8-15
    const uint32_t aLane = (uint32_t)((lane & 15) * ROWB + ((lane >> 4) & 1) * 16);
    // B (16n x 16k per ldsm.x4, NON-trans): m0 n0-7/k0-7, m1 n0-7/k8-15,
    //                                       m2 n8-15/k0-7, m3 n8-15/k8-15
    const uint32_t bLane = (uint32_t)(((lane & 7) + ((lane >> 4) << 3)) * ROWB
                                      + ((lane >> 3) & 1) * 16);
    const uint32_t aWarp = (uint32_t)(wm * 32) * ROWB;
    const uint32_t bWarp = (uint32_t)ASTG + (uint32_t)(wn * 64) * ROWB;

    float acc[2][8][4];
#pragma unroll
    for (int mi = 0; mi < 2; mi++)
#pragma unroll
        for (int nj = 0; nj < 8; nj++)
#pragma unroll
            for (int v = 0; v < 4; v++) acc[mi][nj][v] = 0.0f;

    // prologue: 3 stages in flight
    issue_stage(0, tid, sbase, Agm, BgmH, BgmL);
    issue_stage(1, tid, sbase, Agm, BgmH, BgmL);
    issue_stage(2, tid, sbase, Agm, BgmH, BgmL);

    for (int kt = 0; kt < KT_TOT; kt++) {
        asm volatile("cp.async.wait_group 2;" ::: "memory");
        __syncthreads();
        issue_stage(kt + 3, tid, sbase, Agm, BgmH, BgmL);

        const uint32_t st = sbase + (uint32_t)(kt & 3) * STGB;
#pragma unroll
        for (int s16 = 0; s16 < 2; s16++) {
            uint32_t a[2][4];
#pragma unroll
            for (int mi = 0; mi < 2; mi++) {
                uint32_t addr = st + aWarp + (uint32_t)(mi * 16 * ROWB)
                              + aLane + (uint32_t)(s16 * 32);
                LDSM4(a[mi], addr);
            }
            uint32_t b[4][4];
#pragma unroll
            for (int nj2 = 0; nj2 < 4; nj2++) {
                uint32_t addr = st + bWarp + (uint32_t)(nj2 * 16 * ROWB)
                              + bLane + (uint32_t)(s16 * 32);
                LDSM4(b[nj2], addr);   // NON-trans: smem [n][k] == B col-major
            }
#pragma unroll
            for (int mi = 0; mi < 2; mi++)
#pragma unroll
                for (int nj = 0; nj < 8; nj++) {
                    const uint32_t* bp = &b[nj >> 1][(nj & 1) * 2];
                    MMA16816(acc[mi][nj], a[mi], bp[0], bp[1]);
                }
        }
    }

    // epilogue: fragment layout -> global fp32 + bias
    const int g = lane >> 2;
    const int t = lane & 3;
#pragma unroll
    for (int mi = 0; mi < 2; mi++) {
        const int r0 = mBase + wm * 32 + mi * 16 + g;
#pragma unroll
        for (int nj = 0; nj < 8; nj++) {
            const int col = nBase + wn * 64 + nj * 8 + t * 2;
            const float b0 = __ldg(bias + col);
            const float b1 = __ldg(bias + col + 1);
            float2 v0 = make_float2(acc[mi][nj][0] + b0, acc[mi][nj][1] + b1);
            float2 v1 = make_float2(acc[mi][nj][2] + b0, acc[mi][nj][3] + b1);
            *reinterpret_cast<float2*>(out + (size_t)r0 * OUTF + col) = v0;
            *reinterpret_cast<float2*>(out + (size_t)(r0 + 8) * OUTF + col) = v1;
        }
    }
}

// ---------------------------------------------------------------------------
extern "C" void kernel_launch(void* const* d_in, const int* in_sizes, int n_in,
                              void* d_out, int out_size) {
    (void)in_sizes; (void)n_in; (void)out_size;
    const float* x      = (const float*)d_in[0];
    const int*   qw     = (const int*)d_in[1];
    const float* scales = (const float*)d_in[2];
    const float* zeros  = (const float*)d_in[3];
    const float* bias   = (const float*)d_in[4];
    float* out = (float*)d_out;

    convert_x_kernel<<<TOK * INF / 4 / 256, 256>>>(x);                  // 32768 blocks
    dequant_w_kernel<<<OUTF * INF / 4 / 256, 256>>>(qw, scales, zeros); // 44032 blocks

    static bool attr_set = false;  // host-side only; idempotent, no device state
    if (!attr_set) {
        cudaFuncSetAttribute(gemm_kernel,
                             cudaFuncAttributeMaxDynamicSharedMemorySize, SMEM_BYTES);
        attr_set = true;
    }
    gemm_kernel<<<(TOK / 128) * (OUTF / 128), 256, SMEM_BYTES>>>(bias, out);
}

// round 14
// speedup vs baseline: 1.9175x; 1.9175x over previous
#include <cuda_runtime.h>
#include <cuda_fp16.h>
#include <cstdint>

// ---------------------------------------------------------------------------
// QuantizedLinear: Y[8192,11008] = X[8192,4096] @ dequant(W)^T + bias
// tcgen05 is NOT available (harness PTX target is plain sm_103) -> mma.sync.
// R13 passed with 2-pass W (exact W): rel_err 2.08e-4 == x-fp16 error alone.
// R14: single-pass fp16 W. W fp16 quantization adds an independent ~2e-4
// error in quadrature -> predicted ~3e-4, still 3x under the 1e-3 gate.
// Halves GEMM work: KT_TOT 256 -> 128.
// ---------------------------------------------------------------------------

#define TOK   8192
#define INF   4096
#define OUTF  11008

#define BK      32
#define STAGES  4
#define ROWB    80                  // padded smem row stride (5 x 16B chunks)
#define ASTG    (128 * ROWB)        // 10240 B per A tile
#define STGB    (2 * ASTG)          // 20480 B per stage (A + B)
#define SMEM_BYTES (STAGES * STGB)  // 81920
#define KT_TOT  128                 // single pass over K

// prepped operands (module-load-time scratch; no runtime alloc)
__device__ __align__(128) __half g_X[(size_t)TOK  * INF];   // 67 MB
__device__ __align__(128) __half g_W[(size_t)OUTF * INF];   // 90 MB

// -------------------- prep: x -> fp16 ---------------------------------------
__global__ void convert_x_kernel(const float* __restrict__ x) {
    size_t e = ((size_t)blockIdx.x * 256 + threadIdx.x) * 4;
    float4 v = *reinterpret_cast<const float4*>(x + e);
    __half2 p0 = __halves2half2(__float2half_rn(v.x), __float2half_rn(v.y));
    __half2 p1 = __halves2half2(__float2half_rn(v.z), __float2half_rn(v.w));
    uint2 pk = make_uint2(*reinterpret_cast<uint32_t*>(&p0),
                          *reinterpret_cast<uint32_t*>(&p1));
    *reinterpret_cast<uint2*>(g_X + e) = pk;
}

// -------------------- prep: dequant W -> fp16 --------------------------------
__global__ void dequant_w_kernel(const int* __restrict__ qw,
                                 const float* __restrict__ scales,
                                 const float* __restrict__ zeros) {
    size_t wi = ((size_t)blockIdx.x * 256 + threadIdx.x) * 4;
    int o  = (int)(wi >> 12);        // output feature
    int i0 = (int)(wi & 4095);       // input channel base (multiple of 4)
    int2 qq = *reinterpret_cast<const int2*>(qw + (size_t)o * 2048 + (i0 >> 1));
    int g = i0 >> 7;                 // group of 128 (same for all 4 cols)
    float s = scales[o * 32 + g];
    float z = zeros [o * 32 + g];
    unsigned short h[4];
    h[0] = __half_as_ushort(__float2half_rn(((float)( qq.x       & 15) - z) * s));
    h[1] = __half_as_ushort(__float2half_rn(((float)((qq.x >> 4) & 15) - z) * s));
    h[2] = __half_as_ushort(__float2half_rn(((float)( qq.y       & 15) - z) * s));
    h[3] = __half_as_ushort(__float2half_rn(((float)((qq.y >> 4) & 15) - z) * s));
    *reinterpret_cast<uint2*>(g_W + (size_t)o * INF + i0) =
        make_uint2((uint32_t)h[0] | ((uint32_t)h[1] << 16),
                   (uint32_t)h[2] | ((uint32_t)h[3] << 16));
}

// -------------------- GEMM helpers ------------------------------------------
#define LDSM4(R, addr)                                                        \
    asm volatile("ldmatrix.sync.aligned.m8n8.x4.shared.b16 {%0,%1,%2,%3}, [%4];" \
        : "=r"((R)[0]), "=r"((R)[1]), "=r"((R)[2]), "=r"((R)[3]) : "r"(addr))

#define MMA16816(C, A, B0, B1)                                                \
    asm volatile("mma.sync.aligned.m16n8k16.row.col.f32.f16.f16.f32 "         \
        "{%0,%1,%2,%3}, {%4,%5,%6,%7}, {%8,%9}, {%0,%1,%2,%3};"               \
        : "+f"((C)[0]), "+f"((C)[1]), "+f"((C)[2]), "+f"((C)[3])              \
        : "r"((A)[0]), "r"((A)[1]), "r"((A)[2]), "r"((A)[3]),                 \
          "r"(B0), "r"(B1))

static __device__ __forceinline__ void issue_stage(
    int kt, int tid, uint32_t sbase,
    const __half* __restrict__ Agm,
    const __half* __restrict__ Bgm)
{
    if (kt < KT_TOT) {
        uint32_t st = sbase + (uint32_t)(kt & 3) * STGB;
        int kOff = kt * BK;
#pragma unroll
        for (int j = 0; j < 2; j++) {
            int ch  = tid + j * 256;      // 512 16B-chunks per operand tile
            int row = ch >> 2;
            int c   = ch & 3;
            const void* asrc = Agm + (size_t)row * INF + kOff + c * 8;
            uint32_t    adst = st + row * ROWB + c * 16;
            asm volatile("cp.async.cg.shared.global [%0], [%1], 16;"
                         :: "r"(adst), "l"(asrc));
            const void* bsrc = Bgm + (size_t)row * INF + kOff + c * 8;
            uint32_t    bdst = st + ASTG + row * ROWB + c * 16;
            asm volatile("cp.async.cg.shared.global [%0], [%1], 16;"
                         :: "r"(bdst), "l"(bsrc));
        }
    }
    asm volatile("cp.async.commit_group;" ::: "memory");
}

// -------------------- GEMM kernel -------------------------------------------
// CTA 128x128, 8 warps (4m x 2n), warp tile 32x64, BK=32, 4-stage cp.async.
__global__ void __launch_bounds__(256, 2)
gemm_kernel(const float* __restrict__ bias, float* __restrict__ out) {
    extern __shared__ __align__(1024) uint8_t smem[];
    const int tid  = threadIdx.x;
    const int lane = tid & 31;
    const int wid  = tid >> 5;
    const int wm   = wid >> 1;         // 0..3
    const int wn   = wid & 1;          // 0..1

    // supertile raster: bands of 16 m-tiles, sweep all 86 n-tiles per band
    const int bid   = blockIdx.x;
    const int band  = bid / (16 * 86);
    const int rem   = bid % (16 * 86);
    const int ntile = rem >> 4;
    const int mtile = band * 16 + (rem & 15);
    const int mBase = mtile * 128;
    const int nBase = ntile * 128;

    const __half* Agm = g_X + (size_t)mBase * INF;
    const __half* Bgm = g_W + (size_t)nBase * INF;

    const uint32_t sbase = (uint32_t)__cvta_generic_to_shared(smem);

    // per-lane ldmatrix row addresses (80B rows => (5r+c)%8 covers all banks)
    const uint32_t aLane = (uint32_t)((lane & 15) * ROWB + ((lane >> 4) & 1) * 16);
    // B NON-trans: smem [n][k] row-major == mma.row.col B fragment layout
    const uint32_t bLane = (uint32_t)(((lane & 7) + ((lane >> 4) << 3)) * ROWB
                                      + ((lane >> 3) & 1) * 16);
    const uint32_t aWarp = (uint32_t)(wm * 32) * ROWB;
    const uint32_t bWarp = (uint32_t)ASTG + (uint32_t)(wn * 64) * ROWB;

    float acc[2][8][4];
#pragma unroll
    for (int mi = 0; mi < 2; mi++)
#pragma unroll
        for (int nj = 0; nj < 8; nj++)
#pragma unroll
            for (int v = 0; v < 4; v++) acc[mi][nj][v] = 0.0f;

    // prologue: 3 stages in flight
    issue_stage(0, tid, sbase, Agm, Bgm);
    issue_stage(1, tid, sbase, Agm, Bgm);
    issue_stage(2, tid, sbase, Agm, Bgm);

    for (int kt = 0; kt < KT_TOT; kt++) {
        asm volatile("cp.async.wait_group 2;" ::: "memory");
        __syncthreads();
        issue_stage(kt + 3, tid, sbase, Agm, Bgm);

        const uint32_t st = sbase + (uint32_t)(kt & 3) * STGB;
#pragma unroll
        for (int s16 = 0; s16 < 2; s16++) {
            uint32_t a[2][4];
#pragma unroll
            for (int mi = 0; mi < 2; mi++) {
                uint32_t addr = st + aWarp + (uint32_t)(mi * 16 * ROWB)
                              + aLane + (uint32_t)(s16 * 32);
                LDSM4(a[mi], addr);
            }
            uint32_t b[4][4];
#pragma unroll
            for (int nj2 = 0; nj2 < 4; nj2++) {
                uint32_t addr = st + bWarp + (uint32_t)(nj2 * 16 * ROWB)
                              + bLane + (uint32_t)(s16 * 32);
                LDSM4(b[nj2], addr);
            }
#pragma unroll
            for (int mi = 0; mi < 2; mi++)
#pragma unroll
                for (int nj = 0; nj < 8; nj++) {
                    const uint32_t* bp = &b[nj >> 1][(nj & 1) * 2];
                    MMA16816(acc[mi][nj], a[mi], bp[0], bp[1]);
                }
        }
    }

    // epilogue: fragment layout -> global fp32 + bias
    const int g = lane >> 2;
    const int t = lane & 3;
#pragma unroll
    for (int mi = 0; mi < 2; mi++) {
        const int r0 = mBase + wm * 32 + mi * 16 + g;
#pragma unroll
        for (int nj = 0; nj < 8; nj++) {
            const int col = nBase + wn * 64 + nj * 8 + t * 2;
            const float b0 = __ldg(bias + col);
            const float b1 = __ldg(bias + col + 1);
            float2 v0 = make_float2(acc[mi][nj][0] + b0, acc[mi][nj][1] + b1);
            float2 v1 = make_float2(acc[mi][nj][2] + b0, acc[mi][nj][3] + b1);
            *reinterpret_cast<float2*>(out + (size_t)r0 * OUTF + col) = v0;
            *reinterpret_cast<float2*>(out + (size_t)(r0 + 8) * OUTF + col) = v1;
        }
    }
}

// ---------------------------------------------------------------------------
extern "C" void kernel_launch(void* const* d_in, const int* in_sizes, int n_in,
                              void* d_out, int out_size) {
    (void)in_sizes; (void)n_in; (void)out_size;
    const float* x      = (const float*)d_in[0];
    const int*   qw     = (const int*)d_in[1];
    const float* scales = (const float*)d_in[2];
    const float* zeros  = (const float*)d_in[3];
    const float* bias   = (const float*)d_in[4];
    float* out = (float*)d_out;

    convert_x_kernel<<<TOK * INF / 4 / 256, 256>>>(x);                  // 32768 blocks
    dequant_w_kernel<<<OUTF * INF / 4 / 256, 256>>>(qw, scales, zeros); // 44032 blocks

    static bool attr_set = false;  // host-side only; idempotent, no device state
    if (!attr_set) {
        cudaFuncSetAttribute(gemm_kernel,
                             cudaFuncAttributeMaxDynamicSharedMemorySize, SMEM_BYTES);
        attr_set = true;
    }
    gemm_kernel<<<(TOK / 128) * (OUTF / 128), 256, SMEM_BYTES>>>(bias, out);
}